// round 1
// baseline (speedup 1.0000x reference)
#include <cuda_runtime.h>
#include <math.h>

// ---------------- problem constants ----------------
#define LROW   8192
#define LMASK  8191
#define CC     64
#define NT     512         // threads per fused block
#define TLP    128         // output tile length
#define NY     144         // Prim/y tile: t in [-8, TL+8), offset +8
#define N1     140         // h1 points:   t in [-6, TL+6), offset +6
#define N2     136         // h2 points:   t in [-4, TL+4), offset +4
#define N3     132         // coeffs/grad: t in [-2, TL+2), offset +2
#define DXC    0.015625f   // 1/64
#define INVDX  64.0f
#define CFLC   0.01f

// ---------------- smem layout (float offsets) ----------------
#define OFF_PRIM 0           // 144
#define OFF_Y    144         // 144
#define OFF_W1   288         // 5*64 = 320
#define OFF_B1   608         // 64
#define OFF_B2   672         // 64
#define OFF_B3   736         // 4 (pad 8)
#define OFF_W3   744         // 5*64*4 = 1280
#define OFF_GRAD 2024        // 132 (pad 136)
#define OFF_COEF 2160        // 132*4 = 528
#define OFF_W2   2688        // 5*64*64 = 20480
#define OFF_H1   23168       // 140*64 = 8960
#define OFF_H2   32128       // 136*64 = 8704
#define SMEM_FLOATS 40832    // 163,328 bytes

// ---------------- scratch for per-row min/max ----------------
__device__ float g_mn[2048];
__device__ float g_mx[2048];

// ---------------- static polynomial-accuracy constants ----------------
// alpha_p = solve(vandermonde([-2..2]), e1') = [1/12, -2/3, 0, 2/3, -1/12]
__constant__ float c_alpha_p[5] = {
    0.083333333333333329f, -0.66666666666666663f, 0.0f,
    0.66666666666666663f, -0.083333333333333329f};
// NULL_BASIS = rows 1..4 of Vh from np.linalg.svd([[1,1,1,1,1]])
// (LAPACK Householder completion: col0 = -1/sqrt(5); diag 1-1/(5+sqrt5); off -1/(5+sqrt5))
__constant__ float c_nb[4][5] = {
 {-0.44721359549995793f,  0.86180339887498949f, -0.13819660112501051f, -0.13819660112501051f, -0.13819660112501051f},
 {-0.44721359549995793f, -0.13819660112501051f,  0.86180339887498949f, -0.13819660112501051f, -0.13819660112501051f},
 {-0.44721359549995793f, -0.13819660112501051f, -0.13819660112501051f,  0.86180339887498949f, -0.13819660112501051f},
 {-0.44721359549995793f, -0.13819660112501051f, -0.13819660112501051f, -0.13819660112501051f,  0.86180339887498949f}};

// ================= per-row min/max =================
__global__ void row_minmax(const float* __restrict__ x) {
    int row = blockIdx.x;
    const float4* p = (const float4*)(x + (size_t)row * LROW);
    float mn = INFINITY, mx = -INFINITY;
    for (int i = threadIdx.x; i < LROW / 4; i += blockDim.x) {
        float4 v = p[i];
        mn = fminf(mn, fminf(fminf(v.x, v.y), fminf(v.z, v.w)));
        mx = fmaxf(mx, fmaxf(fmaxf(v.x, v.y), fmaxf(v.z, v.w)));
    }
    #pragma unroll
    for (int off = 16; off; off >>= 1) {
        mn = fminf(mn, __shfl_xor_sync(0xffffffffu, mn, off));
        mx = fmaxf(mx, __shfl_xor_sync(0xffffffffu, mx, off));
    }
    __shared__ float smn[32], smx[32];
    int w = threadIdx.x >> 5, l = threadIdx.x & 31;
    if (l == 0) { smn[w] = mn; smx[w] = mx; }
    __syncthreads();
    if (threadIdx.x < 32) {
        int nw = blockDim.x >> 5;
        mn = (l < nw) ? smn[l] : INFINITY;
        mx = (l < nw) ? smx[l] : -INFINITY;
        #pragma unroll
        for (int off = 16; off; off >>= 1) {
            mn = fminf(mn, __shfl_xor_sync(0xffffffffu, mn, off));
            mx = fmaxf(mx, __shfl_xor_sync(0xffffffffu, mx, off));
        }
        if (l == 0) { g_mn[row] = mn; g_mx[row] = mx; }
    }
}

// ================= fused model kernel =================
__device__ __forceinline__ float phi_fn(float gp, float g) {
    float aa = (g < 0.f) ? -1.f : 1.f;             // min(sign(g),0)*2+1
    float ri = gp / (fmaxf(fabsf(g), 1e-15f) * aa);
    return (ri * ri + ri) / (ri * ri + 1.f);
}

__global__ __launch_bounds__(NT) void fused_kernel(
    const float* __restrict__ Prim,
    const float* __restrict__ W1, const float* __restrict__ B1,
    const float* __restrict__ W2, const float* __restrict__ B2,
    const float* __restrict__ W3, const float* __restrict__ B3,
    float* __restrict__ Out)
{
    extern __shared__ float sm[];
    const int tid = threadIdx.x;
    const int row = blockIdx.y;
    const int i0  = blockIdx.x * TLP;
    const float* prow = Prim + (size_t)row * LROW;

    // ---- cooperative weight loads into smem ----
    {
        const float4* s = (const float4*)W2; float4* d = (float4*)(sm + OFF_W2);
        for (int i = tid; i < 5 * 64 * 64 / 4; i += NT) d[i] = s[i];
    }
    {
        const float4* s = (const float4*)W1; float4* d = (float4*)(sm + OFF_W1);
        for (int i = tid; i < 5 * 64 / 4; i += NT) d[i] = s[i];
    }
    {
        const float4* s = (const float4*)W3; float4* d = (float4*)(sm + OFF_W3);
        for (int i = tid; i < 5 * 64 * 4 / 4; i += NT) d[i] = s[i];
    }
    if (tid < 64) { sm[OFF_B1 + tid] = B1[tid]; sm[OFF_B2 + tid] = B2[tid]; }
    if (tid < 4)  { sm[OFF_B3 + tid] = B3[tid]; }

    // ---- Prim tile + rescale-to-range ----
    float mn = g_mn[row], mx = g_mx[row];
    float inv = 1.0f / fmaxf((mx - mn) * 0.5f, 1e-4f);
    if (tid < NY) {
        float v = prow[(i0 + tid - 8) & LMASK];
        sm[OFF_PRIM + tid] = v;
        sm[OFF_Y + tid]    = (v - mn) * inv - 1.0f;
    }
    __syncthreads();

    // ---- conv1 + tanh : h1[p][c], p in [0, N1) ----
    {
        int c = tid & 63;
        for (int p = tid >> 6; p < N1; p += 8) {
            float acc = sm[OFF_B1 + c];
            #pragma unroll
            for (int k = 0; k < 5; k++)
                acc += sm[OFF_W1 + k * 64 + c] * sm[OFF_Y + p + k];
            sm[OFF_H1 + p * 64 + c] = tanhf(acc);
        }
    }
    __syncthreads();

    // ---- conv2 + tanh : the hot loop (register-blocked, 17 pts/thread) ----
    {
        const int c  = tid & 63;
        const int p0 = (tid >> 6) * 17;       // 8 subs * 17 = 136 = N2 exactly
        float acc[17];
        const float bb = sm[OFF_B2 + c];
        #pragma unroll
        for (int j = 0; j < 17; j++) acc[j] = bb;
        #pragma unroll 1
        for (int k = 0; k < 5; k++) {
            const float* wk = sm + OFF_W2 + k * 4096 + c;   // [ci][c], coalesced over lanes
            const float* hk = sm + OFF_H1 + (p0 + k) * 64;  // broadcast over lanes
            #pragma unroll 2
            for (int ci = 0; ci < 64; ci += 4) {
                float w0 = wk[(ci + 0) * 64];
                float w1 = wk[(ci + 1) * 64];
                float w2 = wk[(ci + 2) * 64];
                float w3 = wk[(ci + 3) * 64];
                #pragma unroll
                for (int j = 0; j < 17; j++) {
                    float4 h = *(const float4*)(hk + j * 64 + ci);
                    acc[j] += w0 * h.x;
                    acc[j] += w1 * h.y;
                    acc[j] += w2 * h.z;
                    acc[j] += w3 * h.w;
                }
            }
        }
        #pragma unroll
        for (int j = 0; j < 17; j++)
            sm[OFF_H2 + (p0 + j) * 64 + c] = tanhf(acc[j]);
    }
    __syncthreads();

    // ---- conv3 : coeffs[p][o], p in [0, N3) ----
    {
        int o = tid & 3;
        int p = tid >> 2;               // 0..127
        for (int pp = p; pp < N3; pp += 128) {
            float acc = sm[OFF_B3 + o];
            #pragma unroll 1
            for (int k = 0; k < 5; k++) {
                const float* wk = sm + OFF_W3 + k * 256 + o;
                const float* hk = sm + OFF_H2 + (pp + k) * 64;
                #pragma unroll 4
                for (int ci = 0; ci < 64; ci += 4) {
                    float4 h = *(const float4*)(hk + ci);
                    acc += wk[(ci + 0) * 4] * h.x;
                    acc += wk[(ci + 1) * 4] * h.y;
                    acc += wk[(ci + 2) * 4] * h.z;
                    acc += wk[(ci + 3) * 4] * h.w;
                }
            }
            sm[OFF_COEF + pp * 4 + o] = acc;
        }
    }
    __syncthreads();

    // ---- alpha + grad_x ----
    if (tid < N3) {
        int p = tid;
        float co0 = sm[OFF_COEF + p * 4 + 0];
        float co1 = sm[OFF_COEF + p * 4 + 1];
        float co2 = sm[OFF_COEF + p * 4 + 2];
        float co3 = sm[OFF_COEF + p * 4 + 3];
        float g = 0.f;
        #pragma unroll
        for (int k = 0; k < 5; k++) {
            float a = c_alpha_p[k] + co0 * c_nb[0][k] + co1 * c_nb[1][k]
                                   + co2 * c_nb[2][k] + co3 * c_nb[3][k];
            g += a * sm[OFF_PRIM + p + 4 + k];   // Prim[t+k-2], t = p-2
        }
        sm[OFF_GRAD + p] = g * INVDX;
    }
    __syncthreads();

    // ---- TVD limiter + Godunov flux + update ----
    if (tid < TLP) {
        int t = tid;
        float g_m2 = sm[OFF_GRAD + t + 0];
        float g_m1 = sm[OFF_GRAD + t + 1];
        float g_0  = sm[OFF_GRAD + t + 2];
        float g_p1 = sm[OFF_GRAD + t + 3];
        float P_m1 = sm[OFF_PRIM + t + 7];
        float P_0  = sm[OFF_PRIM + t + 8];
        float P_p1 = sm[OFF_PRIM + t + 9];

        float phim = phi_fn(g_m2, g_m1);
        float phi0 = phi_fn(g_m1, g_0);
        float phip = phi_fn(g_0,  g_p1);

        float uL1 = P_0  + 0.5f * DXC * phi0 * g_0;
        float uR1 = P_p1 - 0.5f * DXC * phip * g_p1;
        float f1  = 0.25f * (uL1 * uL1 + uR1 * uR1)
                  - 0.25f * fabsf(uL1 + uR1) * (uR1 - uL1);

        float uL0 = P_m1 + 0.5f * DXC * phim * g_m1;
        float uR0 = P_0  - 0.5f * DXC * phi0 * g_0;
        float f0  = 0.25f * (uL0 * uL0 + uR0 * uR0)
                  - 0.25f * fabsf(uL0 + uR0) * (uR0 - uL0);

        Out[(size_t)row * LROW + i0 + t] = P_0 - CFLC * (f1 - f0);
    }
}

// ================= launch =================
extern "C" void kernel_launch(void* const* d_in, const int* in_sizes, int n_in,
                              void* d_out, int out_size) {
    const float* Prim = (const float*)d_in[0];
    const float* W1   = (const float*)d_in[1];
    const float* B1   = (const float*)d_in[2];
    const float* W2   = (const float*)d_in[3];
    const float* B2   = (const float*)d_in[4];
    const float* W3   = (const float*)d_in[5];
    const float* B3   = (const float*)d_in[6];
    int Brows = in_sizes[0] / LROW;

    row_minmax<<<Brows, 256>>>(Prim);

    size_t smem = SMEM_FLOATS * sizeof(float);
    cudaFuncSetAttribute(fused_kernel,
                         cudaFuncAttributeMaxDynamicSharedMemorySize, (int)smem);
    fused_kernel<<<dim3(LROW / TLP, Brows), NT, smem>>>(
        Prim, W1, B1, W2, B2, W3, B3, (float*)d_out);
}